// round 16
// baseline (speedup 1.0000x reference)
#include <cuda_runtime.h>
#include <cuda_bf16.h>
#include <math.h>

#define NPTS     12288
#define DIM      64
#define CDIM     3
#define KNN      85
#define SAMPLE_N 2000
#define HALF_N   6144
#define GAMMA    0.5f
#define SEG      8
#define SEGLEN   (NPTS / SEG)
#define GRID     32
#define NC       (GRID * GRID * GRID)
#define CAPQ     4096
#define MAXROWS  1024
#define CANDCAP  256

// ---------------- device scratch ----------------
__device__ unsigned long long g_packed1[NPTS];
__device__ unsigned long long g_packed2[NPTS];
__device__ int      g_rank1[NPTS];
__device__ int      g_rank2[NPTS];
__device__ int      g_sample_idx[SAMPLE_N];
__device__ float    g_embsT[DIM * SAMPLE_N];
__device__ float    g_csampT[CDIM * SAMPLE_N];
__device__ double   g_acc[6];
__device__ int      g_cellcnt[NC];
__device__ int      g_cellstart[NC + 1];
__device__ int      g_cursor[NC];
__device__ int      g_segsum[32];
__device__ int      g_segoff[33];
__device__ float4   g_pts[NPTS];
__device__ unsigned g_bmin[3], g_bmax[3];

// ---------------- host-side stream fork ----------------
struct StreamPack {
    cudaStream_t side = nullptr;
    cudaEvent_t  evF = nullptr, evJ = nullptr;
    bool ok = false;
    StreamPack() {
        if (cudaStreamCreateWithFlags(&side, cudaStreamNonBlocking) == cudaSuccess &&
            cudaEventCreateWithFlags(&evF, cudaEventDisableTiming) == cudaSuccess &&
            cudaEventCreateWithFlags(&evJ, cudaEventDisableTiming) == cudaSuccess)
            ok = true;
    }
};
static StreamPack g_sp;

// ---------------- threefry2x32-20 ----------------
__host__ __device__ __forceinline__ unsigned int rotl32(unsigned int x, int d) {
    return (x << d) | (x >> (32 - d));
}
__host__ __device__ __forceinline__ void tf2x32(unsigned int k0, unsigned int k1,
                                                unsigned int x0, unsigned int x1,
                                                unsigned int& y0, unsigned int& y1) {
    unsigned int ks0 = k0, ks1 = k1, ks2 = k0 ^ k1 ^ 0x1BD11BDAu;
    x0 += ks0; x1 += ks1;
#define TF_RND(r) { x0 += x1; x1 = rotl32(x1, (r)); x1 ^= x0; }
    TF_RND(13) TF_RND(15) TF_RND(26) TF_RND(6)
    x0 += ks1; x1 += ks2 + 1u;
    TF_RND(17) TF_RND(29) TF_RND(16) TF_RND(24)
    x0 += ks2; x1 += ks0 + 2u;
    TF_RND(13) TF_RND(15) TF_RND(26) TF_RND(6)
    x0 += ks0; x1 += ks1 + 3u;
    TF_RND(17) TF_RND(29) TF_RND(16) TF_RND(24)
    x0 += ks1; x1 += ks2 + 4u;
    TF_RND(13) TF_RND(15) TF_RND(26) TF_RND(6)
    x0 += ks2; x1 += ks0 + 5u;
#undef TF_RND
    y0 = x0; y1 = x1;
}

__device__ __forceinline__ unsigned f2o(float f) {
    unsigned b = __float_as_uint(f);
    return (b & 0x80000000u) ? ~b : (b | 0x80000000u);
}
__device__ __forceinline__ float o2f(unsigned o) {
    unsigned b = (o & 0x80000000u) ? (o & 0x7FFFFFFFu) : ~o;
    return __uint_as_float(b);
}

// ---------------- init / bbox ----------------
__global__ void init_kernel() {
    int g = blockIdx.x * blockDim.x + threadIdx.x;
    int stride = gridDim.x * blockDim.x;
    for (int t = g; t < NC; t += stride) g_cellcnt[t] = 0;
    if (g < NPTS) { g_rank1[g] = 0; g_rank2[g] = 0; }
    if (g < 6) g_acc[g] = 0.0;
    if (g < 3) { g_bmin[g] = 0xFFFFFFFFu; g_bmax[g] = 0u; }
}

__global__ void bbox_kernel(const float* __restrict__ coords) {
    int j = blockIdx.x * blockDim.x + threadIdx.x;
    if (j < NPTS) {
#pragma unroll
        for (int d = 0; d < 3; d++) {
            unsigned o = f2o(coords[3 * j + d]);
            atomicMin(&g_bmin[d], o);
            atomicMax(&g_bmax[d], o);
        }
    }
}

__device__ __forceinline__ void load_grid_params(float lo[3], float inv[3]) {
#pragma unroll
    for (int d = 0; d < 3; d++) {
        float mn = o2f(g_bmin[d]), mx = o2f(g_bmax[d]);
        lo[d] = mn;
        float w = (mx - mn);
        inv[d] = (w > 0.f) ? (float)GRID / w : 0.f;
    }
}
__device__ __forceinline__ int cell_of(float v, float lo, float inv) {
    int c = (int)((v - lo) * inv);
    return min(max(c, 0), GRID - 1);
}

// ---------------- counts / hierarchical prefix / scatter ----------------
__global__ void cellcount_kernel(const float* __restrict__ coords) {
    int j = blockIdx.x * blockDim.x + threadIdx.x;
    if (j >= NPTS) return;
    float lo[3], inv[3];
    load_grid_params(lo, inv);
    int cx = cell_of(coords[3 * j + 0], lo[0], inv[0]);
    int cy = cell_of(coords[3 * j + 1], lo[1], inv[1]);
    int cz = cell_of(coords[3 * j + 2], lo[2], inv[2]);
    atomicAdd(&g_cellcnt[cx + (cy << 5) + (cz << 10)], 1);
}

__global__ void seg_sum_kernel() {
    __shared__ int wt[8];
    int tid = threadIdx.x, lane = tid & 31, wid = tid >> 5;
    const int4* c4 = (const int4*)g_cellcnt;
    int4 c = c4[blockIdx.x * 256 + tid];
    int s = c.x + c.y + c.z + c.w;
#pragma unroll
    for (int o = 16; o > 0; o >>= 1) s += __shfl_down_sync(0xffffffffu, s, o);
    if (lane == 0) wt[wid] = s;
    __syncthreads();
    if (tid == 0) {
        int t = 0;
#pragma unroll
        for (int w = 0; w < 8; w++) t += wt[w];
        g_segsum[blockIdx.x] = t;
    }
}

__global__ void seg_scan_kernel() {
    int lane = threadIdx.x;
    int v = g_segsum[lane];
    int incl = v;
#pragma unroll
    for (int o = 1; o < 32; o <<= 1) {
        int n = __shfl_up_sync(0xffffffffu, incl, o);
        if (lane >= o) incl += n;
    }
    g_segoff[lane] = incl - v;
    if (lane == 31) g_segoff[32] = incl;
}

__global__ void prefix_write_kernel() {
    __shared__ int wt[8];
    int tid = threadIdx.x, lane = tid & 31, wid = tid >> 5;
    const int4* c4 = (const int4*)g_cellcnt;
    int4 c = c4[blockIdx.x * 256 + tid];
    int s = c.x + c.y + c.z + c.w;
    int incl = s;
#pragma unroll
    for (int o = 1; o < 32; o <<= 1) {
        int n = __shfl_up_sync(0xffffffffu, incl, o);
        if (lane >= o) incl += n;
    }
    if (lane == 31) wt[wid] = incl;
    __syncthreads();
    int woff = 0;
    for (int w = 0; w < wid; w++) woff += wt[w];
    int base = g_segoff[blockIdx.x] + woff + incl - s;
    int4 o4;
    o4.x = base;
    o4.y = base + c.x;
    o4.z = base + c.x + c.y;
    o4.w = base + c.x + c.y + c.z;
    ((int4*)g_cellstart)[blockIdx.x * 256 + tid] = o4;
    ((int4*)g_cursor)[blockIdx.x * 256 + tid] = o4;
    if (blockIdx.x == 31 && tid == 255) g_cellstart[NC] = g_segoff[32];
}

__global__ void scatter_kernel(const float* __restrict__ coords) {
    int j = blockIdx.x * blockDim.x + threadIdx.x;
    if (j >= NPTS) return;
    float lo[3], inv[3];
    load_grid_params(lo, inv);
    float x = coords[3 * j + 0], y = coords[3 * j + 1], z = coords[3 * j + 2];
    int c = cell_of(x, lo[0], inv[0]) + (cell_of(y, lo[1], inv[1]) << 5)
          + (cell_of(z, lo[2], inv[2]) << 10);
    int pos = atomicAdd(&g_cursor[c], 1);
    g_pts[pos] = make_float4(x, y, z, __int_as_float(j));
}

// ---------------- SAT ----------------
__global__ void __launch_bounds__(128) sat_x_kernel() {
    int t = blockIdx.x * 128 + threadIdx.x;
    int4* p = (int4*)(g_cellcnt + (t << 5));
    int4 v[8];
#pragma unroll
    for (int u = 0; u < 8; u++) v[u] = p[u];
    int acc = 0;
#pragma unroll
    for (int u = 0; u < 8; u++) {
        v[u].x += acc; v[u].y += v[u].x; v[u].z += v[u].y; v[u].w += v[u].z;
        acc = v[u].w;
    }
#pragma unroll
    for (int u = 0; u < 8; u++) p[u] = v[u];
}
__global__ void __launch_bounds__(128) sat_y_kernel() {
    int t = blockIdx.x * 128 + threadIdx.x;
    int x = t & 31, z = t >> 5;
    int b = x + (z << 10);
    int a[32];
#pragma unroll
    for (int y = 0; y < GRID; y++) a[y] = g_cellcnt[b + (y << 5)];
    int acc = 0;
#pragma unroll
    for (int y = 0; y < GRID; y++) { acc += a[y]; a[y] = acc; }
#pragma unroll
    for (int y = 0; y < GRID; y++) g_cellcnt[b + (y << 5)] = a[y];
}
__global__ void __launch_bounds__(128) sat_z_kernel() {
    int t = blockIdx.x * 128 + threadIdx.x;
    int a[32];
#pragma unroll
    for (int z = 0; z < GRID; z++) a[z] = g_cellcnt[t + (z << 10)];
    int acc = 0;
#pragma unroll
    for (int z = 0; z < GRID; z++) { acc += a[z]; a[z] = acc; }
#pragma unroll
    for (int z = 0; z < GRID; z++) g_cellcnt[t + (z << 10)] = a[z];
}

__device__ __forceinline__ int satv(int x, int y, int z) {
    if (x < 0 || y < 0 || z < 0) return 0;
    return g_cellcnt[x + (y << 5) + (z << 10)];
}
__device__ __forceinline__ int boxcount(int x0, int x1, int y0, int y1, int z0, int z1) {
    return satv(x1, y1, z1) - satv(x0 - 1, y1, z1) - satv(x1, y0 - 1, z1) - satv(x1, y1, z0 - 1)
         + satv(x0 - 1, y0 - 1, z1) + satv(x0 - 1, y1, z0 - 1) + satv(x1, y0 - 1, z0 - 1)
         - satv(x0 - 1, y0 - 1, z0 - 1);
}

// ---------------- permutation via rank (proven) ----------------
__global__ void permA_kernel(unsigned int k0, unsigned int k1) {
    int l = blockIdx.x * blockDim.x + threadIdx.x;
    if (l < HALF_N) {
        unsigned int y0, y1;
        tf2x32(k0, k1, (unsigned int)l, (unsigned int)(l + HALF_N), y0, y1);
        g_packed1[l]          = ((unsigned long long)y0 << 14) | (unsigned int)l;
        g_packed1[l + HALF_N] = ((unsigned long long)y1 << 14) | (unsigned int)(l + HALF_N);
    }
}
__global__ void rank_partial_kernel(const unsigned long long* __restrict__ keys,
                                    int* __restrict__ rank) {
    __shared__ unsigned long long tile[256];
    int j = blockIdx.x * 256 + threadIdx.x;
    unsigned long long mk = __ldg(&keys[j]);
    int base0 = blockIdx.y * SEGLEN;
    int cnt = 0;
    for (int base = base0; base < base0 + SEGLEN; base += 256) {
        tile[threadIdx.x] = __ldg(&keys[base + threadIdx.x]);
        __syncthreads();
#pragma unroll 8
        for (int u = 0; u < 256; u++) cnt += (tile[u] < mk) ? 1 : 0;
        __syncthreads();
    }
    atomicAdd(&rank[j], cnt);
}
__global__ void permB_gen_kernel(unsigned int k0, unsigned int k1) {
    int j = blockIdx.x * blockDim.x + threadIdx.x;
    int r = g_rank1[j];
    int lane = (r < HALF_N) ? r : (r - HALF_N);
    unsigned int y0, y1;
    tf2x32(k0, k1, (unsigned int)lane, (unsigned int)(lane + HALF_N), y0, y1);
    unsigned int bits = (r < HALF_N) ? y0 : y1;
    g_packed2[j] = ((unsigned long long)bits << 14) | (unsigned int)r;
}
__global__ void permC_gen_kernel() {
    int j = blockIdx.x * blockDim.x + threadIdx.x;
    int r2 = g_rank2[j];
    if (r2 < SAMPLE_N) g_sample_idx[r2] = j;
}

// ---------------- gather ----------------
__global__ void gather_kernel(const float* __restrict__ emb, const float* __restrict__ coords) {
    int stride = gridDim.x * blockDim.x;
    int gid = blockIdx.x * blockDim.x + threadIdx.x;
    for (int t = gid; t < SAMPLE_N * DIM; t += stride) {
        int s = t / DIM, d = t - s * DIM;
        g_embsT[d * SAMPLE_N + s] = emb[(long)g_sample_idx[s] * DIM + d];
    }
    for (int t = gid; t < SAMPLE_N * CDIM; t += stride) {
        int s = t / CDIM, c = t - s * CDIM;
        g_csampT[c * SAMPLE_N + s] = coords[(long)g_sample_idx[s] * CDIM + c];
    }
}

// ---------------- reductions ----------------
__device__ void block_reduce_atomic_256(double v, double* target, double* swarp) {
    int lane = threadIdx.x & 31, wid = threadIdx.x >> 5;
#pragma unroll
    for (int o = 16; o > 0; o >>= 1) v += __shfl_down_sync(0xffffffffu, v, o);
    if (lane == 0) swarp[wid] = v;
    __syncthreads();
    if (wid == 0) {
        double r = (lane < 8) ? swarp[lane] : 0.0;
#pragma unroll
        for (int o = 4; o > 0; o >>= 1) r += __shfl_down_sync(0xffffffffu, r, o);
        if (lane == 0) atomicAdd(target, r);
    }
    __syncthreads();
}

// ---------------- pearson (proven) ----------------
#define TI 8
__global__ void pearson_kernel(const float* __restrict__ emb, const float* __restrict__ coords) {
    __shared__ float semb[TI][DIM];
    __shared__ float scrd[TI][CDIM];
    __shared__ double swarp[8];
    int i0 = blockIdx.x * TI;
    for (int t = threadIdx.x; t < TI * DIM; t += blockDim.x) {
        int r = t / DIM, d = t - r * DIM;
        semb[r][d] = emb[(long)g_sample_idx[i0 + r] * DIM + d];
    }
    for (int t = threadIdx.x; t < TI * CDIM; t += blockDim.x) {
        int r = t / CDIM, c = t - r * CDIM;
        scrd[r][c] = coords[(long)g_sample_idx[i0 + r] * CDIM + c];
    }
    __syncthreads();

    double se = 0, sc = 0, see = 0, scc = 0, sec = 0;
    for (int j = threadIdx.x; j < SAMPLE_N; j += blockDim.x) {
        float sq[TI];
#pragma unroll
        for (int r = 0; r < TI; r++) sq[r] = 0.f;
#pragma unroll 4
        for (int d = 0; d < DIM; d++) {
            float ej = g_embsT[d * SAMPLE_N + j];
#pragma unroll
            for (int r = 0; r < TI; r++) {
                float df = semb[r][d] - ej;
                sq[r] = fmaf(df, df, sq[r]);
            }
        }
        float cj0 = g_csampT[j];
        float cj1 = g_csampT[SAMPLE_N + j];
        float cj2 = g_csampT[2 * SAMPLE_N + j];
#pragma unroll
        for (int r = 0; r < TI; r++) {
            float d0 = scrd[r][0] - cj0, d1 = scrd[r][1] - cj1, d2 = scrd[r][2] - cj2;
            float cd = sqrtf(fmaf(d0, d0, fmaf(d1, d1, d2 * d2)));
            float ed = sqrtf(sq[r]);
            se += (double)ed;
            sc += (double)cd;
            see += (double)ed * (double)ed;
            scc += (double)cd * (double)cd;
            sec += (double)ed * (double)cd;
        }
    }
    block_reduce_atomic_256(se,  &g_acc[0], swarp);
    block_reduce_atomic_256(sc,  &g_acc[1], swarp);
    block_reduce_atomic_256(see, &g_acc[2], swarp);
    block_reduce_atomic_256(scc, &g_acc[3], swarp);
    block_reduce_atomic_256(sec, &g_acc[4], swarp);
}

// ---------------- flat parallel range collect (proven, 128 thr) ----------------
__device__ int collect_range(int x0, int x1, int y0, int y1, int z0, int z1,
                             float q0, float q1, float q2,
                             float* bufD, int* bufI,
                             int* rowoff, int* rowstart, int* warptot) {
    int tid = threadIdx.x, lane = tid & 31, wid = tid >> 5;
    int ny = y1 - y0 + 1, nz = z1 - z0 + 1;
    int nrows = ny * nz;
    int chunk = (nrows + 127) >> 7;
    int myv[8];
    int s = 0;
    for (int u = 0; u < chunk; u++) {
        int r = tid * chunk + u;
        int v = 0;
        if (r < nrows) {
            int y = y0 + (r % ny), z = z0 + (r / ny);
            int c = x0 + (y << 5) + (z << 10);
            int cs = g_cellstart[c];
            int ce = g_cellstart[c + (x1 - x0) + 1];
            rowstart[r] = cs;
            v = ce - cs;
        }
        myv[u] = v;
        s += v;
    }
    int v2 = s;
#pragma unroll
    for (int o = 1; o < 32; o <<= 1) {
        int n = __shfl_up_sync(0xffffffffu, v2, o);
        if (lane >= o) v2 += n;
    }
    if (lane == 31) warptot[wid] = v2;
    __syncthreads();
    int woff = 0;
    for (int w = 0; w < wid; w++) woff += warptot[w];
    int run = woff + v2 - s;
    for (int u = 0; u < chunk; u++) {
        int r = tid * chunk + u;
        if (r < nrows) { rowoff[r] = run; run += myv[u]; }
    }
    if (tid == 127) rowoff[nrows] = warptot[0] + warptot[1] + warptot[2] + warptot[3];
    __syncthreads();
    int M = rowoff[nrows];
    if (M > CAPQ) { __syncthreads(); return M; }

    for (int t = tid; t < M; t += 128) {
        int lo = 0, hi = nrows - 1;
        while (lo < hi) {
            int mid = (lo + hi + 1) >> 1;
            if (rowoff[mid] <= t) lo = mid; else hi = mid - 1;
        }
        int p = rowstart[lo] + (t - rowoff[lo]);
        float4 pt = g_pts[p];
        float dx = q0 - pt.x, dy = q1 - pt.y, dz = q2 - pt.z;
        bufD[t] = fmaf(dx, dx, fmaf(dy, dy, dz * dz));
        bufI[t] = __float_as_int(pt.w);
    }
    __syncthreads();
    return M;
}

// O(M²) fallback select (exact, rare)
__device__ float select_rank_slow(const float* bufD, int M, int rank, float* s_tau) {
    int tid = threadIdx.x;
    for (int ii = tid; ii < M; ii += 128) {
        float e = bufD[ii];
        int l = 0, le = 0;
        for (int j2 = 0; j2 < M; j2++) {
            float b = bufD[j2];
            l  += (b < e)  ? 1 : 0;
            le += (b <= e) ? 1 : 0;
        }
        if (l < rank && rank <= le) *s_tau = e;
    }
    __syncthreads();
    return *s_tau;
}

// O(M) exact select (proven R8)
__device__ float select_rank_hist(const float* bufD, int M, int rank,
                                  int* hist, int* warptot,
                                  int* s_bin, int* s_cum, int* s_c, float* s_tau) {
    int tid = threadIdx.x, lane = tid & 31, wid = tid >> 5;
    for (int k = tid; k < 2048; k += 128) hist[k] = 0;
    if (tid == 0) *s_c = 0;
    __syncthreads();
    for (int t = tid; t < M; t += 128)
        atomicAdd(&hist[__float_as_uint(bufD[t]) >> 20], 1);
    __syncthreads();
    {
        int base = tid * 16;
        int h[16], s = 0;
#pragma unroll
        for (int u = 0; u < 16; u++) { h[u] = hist[base + u]; s += h[u]; }
        int v = s;
#pragma unroll
        for (int o = 1; o < 32; o <<= 1) {
            int n = __shfl_up_sync(0xffffffffu, v, o);
            if (lane >= o) v += n;
        }
        if (lane == 31) warptot[wid] = v;
        __syncthreads();
        int woff = 0;
        for (int w = 0; w < wid; w++) woff += warptot[w];
        int incl = woff + v, excl = incl - s;
        if (excl < rank && rank <= incl) {
            int c = excl;
#pragma unroll
            for (int u = 0; u < 16; u++) {
                if (rank <= c + h[u]) { *s_bin = base + u; *s_cum = c; break; }
                c += h[u];
            }
        }
        __syncthreads();
    }
    int b = *s_bin;
    int rb = rank - *s_cum;
    float* cand = (float*)hist;
    __syncthreads();
    int iters = (M + 127) >> 7;
    for (int it = 0; it < iters; it++) {
        int t = (it << 7) + tid;
        float v = 0.f;
        bool in = false;
        if (t < M) {
            v = bufD[t];
            in = ((int)(__float_as_uint(v) >> 20) == b);
        }
        unsigned m = __ballot_sync(0xffffffffu, in);
        if (in) {
            int ldr = __ffs(m) - 1;
            int basep = 0;
            if (lane == ldr) basep = atomicAdd(s_c, __popc(m));
            basep = __shfl_sync(m, basep, ldr);
            int p = basep + __popc(m & ((1u << lane) - 1u));
            if (p < CANDCAP) cand[p] = v;
        }
    }
    __syncthreads();
    int C = *s_c;
    if (C > CANDCAP) return select_rank_slow(bufD, M, rank, s_tau);
    for (int ii = tid; ii < C; ii += 128) {
        float e = cand[ii];
        int l = 0, le = 0;
        for (int j2 = 0; j2 < C; j2++) {
            float bb = cand[j2];
            l  += (bb < e)  ? 1 : 0;
            le += (bb <= e) ? 1 : 0;
        }
        if (l < rb && rb <= le) *s_tau = e;
    }
    __syncthreads();
    return *s_tau;
}

// ---------------- query kernel: 128 thr/row, SPATIALLY-ORDERED queries ----------------
__global__ void __launch_bounds__(128)
knn_query_kernel(const float* __restrict__ emb, const float* __restrict__ coords) {
    __shared__ float bufD[CAPQ];
    __shared__ int   bufI[CAPQ];
    __shared__ int   rowoff[MAXROWS + 1];
    __shared__ int   rowstart[MAXROWS];
    __shared__ int   hist[2048];
    __shared__ float ei[DIM];
    __shared__ int   warptot[4];
    __shared__ int   s_s1, s_W, s_icnt, s_bin, s_cum, s_c;
    __shared__ float s_tau;
    __shared__ double swarpd[4];

    int tid = threadIdx.x;
    int lane = tid & 31, wid = tid >> 5;

    // R15: query = cell-sorted point blockIdx.x -> concurrent blocks are spatial
    // neighbors (L2-hot cellstart/pts, homogeneous waves). Original row index in .w.
    float4 qp = g_pts[blockIdx.x];
    float q0 = qp.x, q1 = qp.y, q2 = qp.z;
    int i = __float_as_int(qp.w);
    if (tid < DIM) ei[tid] = emb[(long)i * DIM + tid];

    float lo[3], inv[3];
    load_grid_params(lo, inv);
    int qcx = cell_of(q0, lo[0], inv[0]);
    int qcy = cell_of(q1, lo[1], inv[1]);
    int qcz = cell_of(q2, lo[2], inv[2]);

    int myc = 0;
    if (tid < 16) {
        int s = tid;
        myc = boxcount(max(qcx - s, 0), min(qcx + s, GRID - 1),
                       max(qcy - s, 0), min(qcy + s, GRID - 1),
                       max(qcz - s, 0), min(qcz + s, GRID - 1));
    }
    unsigned ok = __ballot_sync(0xffffffffu, tid < 16 && myc >= KNN + 2);
    if (tid == 0) {
        if (ok) s_s1 = __ffs(ok) - 1;
        else {
            int s = 16;
            while (s < GRID && boxcount(max(qcx - s, 0), min(qcx + s, GRID - 1),
                                        max(qcy - s, 0), min(qcy + s, GRID - 1),
                                        max(qcz - s, 0), min(qcz + s, GRID - 1)) < KNN + 2) s++;
            s_s1 = s;
        }
    }
    __syncthreads();
    int s1 = s_s1 + 1;

    int bx0 = max(qcx - s1, 0), bx1 = min(qcx + s1, GRID - 1);
    int by0 = max(qcy - s1, 0), by1 = min(qcy + s1, GRID - 1);
    int bz0 = max(qcz - s1, 0), bz1 = min(qcz + s1, GRID - 1);

    int M = collect_range(bx0, bx1, by0, by1, bz0, bz1, q0, q1, q2,
                          bufD, bufI, rowoff, rowstart, warptot);
    bool overflow = (M > CAPQ);
    float tau = 0.f;
    bool done = false;

    if (!overflow) {
        float tau1 = select_rank_hist(bufD, M, KNN + 1, hist, warptot,
                                      &s_bin, &s_cum, &s_c, &s_tau);
        float R = sqrtf(tau1) * 1.0001f + 1e-7f;

        float w0 = 1.f / inv[0], w1 = 1.f / inv[1], w2 = 1.f / inv[2];
        bool cont = true;
        if (bx0 > 0)        cont = cont && (q0 - R >= lo[0] + bx0 * w0);
        if (bx1 < GRID - 1) cont = cont && (q0 + R <= lo[0] + (bx1 + 1) * w0);
        if (by0 > 0)        cont = cont && (q1 - R >= lo[1] + by0 * w1);
        if (by1 < GRID - 1) cont = cont && (q1 + R <= lo[1] + (by1 + 1) * w1);
        if (bz0 > 0)        cont = cont && (q2 - R >= lo[2] + bz0 * w2);
        if (bz1 < GRID - 1) cont = cont && (q2 + R <= lo[2] + (bz1 + 1) * w2);

        if (cont) {
            tau = tau1;
            done = true;
        } else {
            int x0 = min(max((int)floorf((q0 - R - lo[0]) * inv[0]), 0), GRID - 1);
            int x1 = min(max((int)floorf((q0 + R - lo[0]) * inv[0]), 0), GRID - 1);
            int y0 = min(max((int)floorf((q1 - R - lo[1]) * inv[1]), 0), GRID - 1);
            int y1 = min(max((int)floorf((q1 + R - lo[1]) * inv[1]), 0), GRID - 1);
            int z0 = min(max((int)floorf((q2 - R - lo[2]) * inv[2]), 0), GRID - 1);
            int z1 = min(max((int)floorf((q2 + R - lo[2]) * inv[2]), 0), GRID - 1);
            __syncthreads();
            M = collect_range(x0, x1, y0, y1, z0, z1, q0, q1, q2,
                              bufD, bufI, rowoff, rowstart, warptot);
            overflow = (M > CAPQ);
            if (!overflow) {
                tau = select_rank_hist(bufD, M, KNN + 1, hist, warptot,
                                       &s_bin, &s_cum, &s_c, &s_tau);
                done = true;
            }
        }
    }

    double acc = 0.0;
    if (done) {
        if (tid == 0) s_W = 0;
        __syncthreads();
        float* wd2 = (float*)rowoff;
        int*   wix = rowstart;
        int iters = (M + 127) >> 7;
        for (int it2 = 0; it2 < iters; it2++) {
            int t = (it2 << 7) + tid;
            float d2 = 0.f; int idx = 0;
            bool win = false;
            if (t < M) {
                d2 = bufD[t];
                idx = bufI[t];
                win = (d2 <= tau) && (idx != i);
            }
            unsigned m = __ballot_sync(0xffffffffu, win);
            if (win) {
                int ldr = __ffs(m) - 1;
                int basep = 0;
                if (lane == ldr) basep = atomicAdd(&s_W, __popc(m));
                basep = __shfl_sync(m, basep, ldr);
                int p = basep + __popc(m & ((1u << lane) - 1u));
                if (p < MAXROWS) { wd2[p] = d2; wix[p] = idx; }
            }
        }
        __syncthreads();
        int W = min(s_W, MAXROWS);
        for (int w = tid; w < W; w += 128) {
            float t = sqrtf(wd2[w]);
            int j = wix[w];
            const float4* e4 = (const float4*)(emb + (long)j * DIM);
            const float4* a4 = (const float4*)ei;
            float s = 0.f;
#pragma unroll
            for (int u = 0; u < DIM / 4; u++) {
                float4 a = a4[u];
                float4 b = e4[u];
                float d0 = a.x - b.x, dd1 = a.y - b.y, dd2 = a.z - b.z, d3 = a.w - b.w;
                s = fmaf(d0, d0, fmaf(dd1, dd1, fmaf(dd2, dd2, fmaf(d3, d3, s))));
            }
            float p = sqrtf(s);
            float df = p - t;
            acc += (double)(df * df * expf(-GAMMA * t));
        }
    } else {
        unsigned int lob = 0u, hib = 0x7F800000u;
        while (lob < hib) {
            unsigned int mid = (lob + hib) >> 1;
            float midf = __uint_as_float(mid);
            int c = 0;
            for (int j = tid; j < NPTS; j += 128) {
                float dx = q0 - coords[3 * j], dy = q1 - coords[3 * j + 1], dz = q2 - coords[3 * j + 2];
                float d2 = fmaf(dx, dx, fmaf(dy, dy, dz * dz));
                c += (d2 <= midf) ? 1 : 0;
            }
#pragma unroll
            for (int o = 16; o > 0; o >>= 1) c += __shfl_down_sync(0xffffffffu, c, o);
            if (lane == 0) warptot[wid] = c;
            __syncthreads();
            if (tid == 0) s_icnt = warptot[0] + warptot[1] + warptot[2] + warptot[3];
            __syncthreads();
            if (s_icnt >= KNN + 1) hib = mid; else lob = mid + 1;
        }
        float tf = __uint_as_float(lob);
        for (int j = tid; j < NPTS; j += 128) {
            float dx = q0 - coords[3 * j], dy = q1 - coords[3 * j + 1], dz = q2 - coords[3 * j + 2];
            float d2 = fmaf(dx, dx, fmaf(dy, dy, dz * dz));
            if (d2 <= tf && j != i) {
                float t = sqrtf(d2);
                const float4* e4 = (const float4*)(emb + (long)j * DIM);
                const float4* a4 = (const float4*)ei;
                float s = 0.f;
#pragma unroll
                for (int u = 0; u < DIM / 4; u++) {
                    float4 a = a4[u];
                    float4 b = e4[u];
                    float d0 = a.x - b.x, dd1 = a.y - b.y, dd2 = a.z - b.z, d3 = a.w - b.w;
                    s = fmaf(d0, d0, fmaf(dd1, dd1, fmaf(dd2, dd2, fmaf(d3, d3, s))));
                }
                float p = sqrtf(s);
                float df = p - t;
                acc += (double)(df * df * expf(-GAMMA * t));
            }
        }
    }

#pragma unroll
    for (int o = 16; o > 0; o >>= 1) acc += __shfl_down_sync(0xffffffffu, acc, o);
    if (lane == 0) swarpd[wid] = acc;
    __syncthreads();
    if (tid == 0) {
        double r = swarpd[0] + swarpd[1] + swarpd[2] + swarpd[3];
        atomicAdd(&g_acc[5], r);
    }
}

// ---------------- finalize ----------------
__global__ void finalize_kernel(float* out) {
    double M = (double)SAMPLE_N * (double)SAMPLE_N;
    double se = g_acc[0], sc = g_acc[1], see = g_acc[2], scc = g_acc[3], sec = g_acc[4];
    double ls = g_acc[5];
    double me = se / M, mc = sc / M;
    double cov = sec / M - me * mc;
    double ve = see / M - me * me;
    double vc = scc / M - mc * mc;
    double es = sqrt(ve + 1e-8);
    double cs = sqrt(vc + 1e-8);
    double pearson = cov / (es * cs + 1e-8);
    double local = ls / ((double)NPTS * (double)KNN);
    out[0] = (float)((1.0 - pearson) + 0.5 * local);
}

// ---------------- launch ----------------
extern "C" void kernel_launch(void* const* d_in, const int* in_sizes, int n_in,
                              void* d_out, int out_size) {
    const float* emb;
    const float* coords;
    if (in_sizes[0] == NPTS * DIM) {
        emb = (const float*)d_in[0];
        coords = (const float*)d_in[1];
    } else {
        emb = (const float*)d_in[1];
        coords = (const float*)d_in[0];
    }
    float* out = (float*)d_out;

    unsigned int a0, b0, a1, b1;
    tf2x32(0u, 42u, 0u, 2u, a0, b0);
    tf2x32(0u, 42u, 1u, 3u, a1, b1);
    unsigned int c0, d0, c1, d1;
    tf2x32(a0, a1, 0u, 2u, c0, d0);
    tf2x32(a0, a1, 1u, 3u, c1, d1);

    unsigned long long* p1; cudaGetSymbolAddress((void**)&p1, g_packed1);
    unsigned long long* p2; cudaGetSymbolAddress((void**)&p2, g_packed2);
    int* r1; cudaGetSymbolAddress((void**)&r1, g_rank1);
    int* r2; cudaGetSymbolAddress((void**)&r2, g_rank2);
    dim3 rg(NPTS / 256, SEG);

    bool fork = g_sp.ok;
    cudaStream_t sm = 0;
    cudaStream_t ss = fork ? g_sp.side : (cudaStream_t)0;

    init_kernel<<<NPTS / 256, 256, 0, sm>>>();

    if (fork) {
        cudaEventRecord(g_sp.evF, sm);
        cudaStreamWaitEvent(ss, g_sp.evF, 0);
    }

    // ---- Chain B (side): permutation -> gather -> pearson ----
    permA_kernel<<<HALF_N / 256, 256, 0, ss>>>(b0, b1);
    rank_partial_kernel<<<rg, 256, 0, ss>>>(p1, r1);
    permB_gen_kernel<<<NPTS / 256, 256, 0, ss>>>(d0, d1);
    rank_partial_kernel<<<rg, 256, 0, ss>>>(p2, r2);
    permC_gen_kernel<<<NPTS / 256, 256, 0, ss>>>();
    gather_kernel<<<160, 256, 0, ss>>>(emb, coords);
    pearson_kernel<<<SAMPLE_N / TI, 256, 0, ss>>>(emb, coords);

    // ---- Chain A (main): grid build -> knn ----
    bbox_kernel<<<NPTS / 256, 256, 0, sm>>>(coords);
    cellcount_kernel<<<NPTS / 256, 256, 0, sm>>>(coords);
    seg_sum_kernel<<<32, 256, 0, sm>>>();
    seg_scan_kernel<<<1, 32, 0, sm>>>();
    prefix_write_kernel<<<32, 256, 0, sm>>>();
    scatter_kernel<<<NPTS / 256, 256, 0, sm>>>(coords);
    sat_x_kernel<<<8, 128, 0, sm>>>();
    sat_y_kernel<<<8, 128, 0, sm>>>();
    sat_z_kernel<<<8, 128, 0, sm>>>();
    knn_query_kernel<<<NPTS, 128, 0, sm>>>(emb, coords);

    if (fork) {
        cudaEventRecord(g_sp.evJ, ss);
        cudaStreamWaitEvent(sm, g_sp.evJ, 0);
    }

    finalize_kernel<<<1, 1, 0, sm>>>(out);
}

// round 17
// speedup vs baseline: 1.1640x; 1.1640x over previous
#include <cuda_runtime.h>
#include <cuda_bf16.h>
#include <math.h>

#define NPTS     12288
#define DIM      64
#define CDIM     3
#define KNN      85
#define SAMPLE_N 2000
#define HALF_N   6144
#define GAMMA    0.5f
#define SEG      8
#define SEGLEN   (NPTS / SEG)
#define GRID     32
#define NC       (GRID * GRID * GRID)
#define CAPQ     2048
#define MAXROWS  512
#define CANDCAP  256

// ---------------- device scratch ----------------
__device__ unsigned long long g_packed1[NPTS];
__device__ unsigned long long g_packed2[NPTS];
__device__ int      g_rank1[NPTS];
__device__ int      g_rank2[NPTS];
__device__ int      g_sample_idx[SAMPLE_N];
__device__ float    g_embsT[DIM * SAMPLE_N];
__device__ float    g_csampT[CDIM * SAMPLE_N];
__device__ double   g_acc[6];
__device__ int      g_cellcnt[NC];
__device__ int      g_cellstart[NC + 1];
__device__ int      g_cursor[NC];
__device__ int      g_segsum[32];
__device__ int      g_segoff[33];
__device__ float4   g_pts[NPTS];
__device__ unsigned g_bmin[3], g_bmax[3];

// ---------------- host-side stream fork ----------------
struct StreamPack {
    cudaStream_t side = nullptr;
    cudaEvent_t  evF = nullptr, evJ = nullptr;
    bool ok = false;
    StreamPack() {
        if (cudaStreamCreateWithFlags(&side, cudaStreamNonBlocking) == cudaSuccess &&
            cudaEventCreateWithFlags(&evF, cudaEventDisableTiming) == cudaSuccess &&
            cudaEventCreateWithFlags(&evJ, cudaEventDisableTiming) == cudaSuccess)
            ok = true;
    }
};
static StreamPack g_sp;

// ---------------- threefry2x32-20 ----------------
__host__ __device__ __forceinline__ unsigned int rotl32(unsigned int x, int d) {
    return (x << d) | (x >> (32 - d));
}
__host__ __device__ __forceinline__ void tf2x32(unsigned int k0, unsigned int k1,
                                                unsigned int x0, unsigned int x1,
                                                unsigned int& y0, unsigned int& y1) {
    unsigned int ks0 = k0, ks1 = k1, ks2 = k0 ^ k1 ^ 0x1BD11BDAu;
    x0 += ks0; x1 += ks1;
#define TF_RND(r) { x0 += x1; x1 = rotl32(x1, (r)); x1 ^= x0; }
    TF_RND(13) TF_RND(15) TF_RND(26) TF_RND(6)
    x0 += ks1; x1 += ks2 + 1u;
    TF_RND(17) TF_RND(29) TF_RND(16) TF_RND(24)
    x0 += ks2; x1 += ks0 + 2u;
    TF_RND(13) TF_RND(15) TF_RND(26) TF_RND(6)
    x0 += ks0; x1 += ks1 + 3u;
    TF_RND(17) TF_RND(29) TF_RND(16) TF_RND(24)
    x0 += ks1; x1 += ks2 + 4u;
    TF_RND(13) TF_RND(15) TF_RND(26) TF_RND(6)
    x0 += ks2; x1 += ks0 + 5u;
#undef TF_RND
    y0 = x0; y1 = x1;
}

__device__ __forceinline__ unsigned f2o(float f) {
    unsigned b = __float_as_uint(f);
    return (b & 0x80000000u) ? ~b : (b | 0x80000000u);
}
__device__ __forceinline__ float o2f(unsigned o) {
    unsigned b = (o & 0x80000000u) ? (o & 0x7FFFFFFFu) : ~o;
    return __uint_as_float(b);
}

// ---------------- init / bbox ----------------
__global__ void init_kernel() {
    int g = blockIdx.x * blockDim.x + threadIdx.x;
    int stride = gridDim.x * blockDim.x;
    for (int t = g; t < NC; t += stride) g_cellcnt[t] = 0;
    if (g < NPTS) { g_rank1[g] = 0; g_rank2[g] = 0; }
    if (g < 6) g_acc[g] = 0.0;
    if (g < 3) { g_bmin[g] = 0xFFFFFFFFu; g_bmax[g] = 0u; }
}

__global__ void bbox_kernel(const float* __restrict__ coords) {
    int j = blockIdx.x * blockDim.x + threadIdx.x;
    if (j < NPTS) {
#pragma unroll
        for (int d = 0; d < 3; d++) {
            unsigned o = f2o(coords[3 * j + d]);
            atomicMin(&g_bmin[d], o);
            atomicMax(&g_bmax[d], o);
        }
    }
}

__device__ __forceinline__ void load_grid_params(float lo[3], float inv[3]) {
#pragma unroll
    for (int d = 0; d < 3; d++) {
        float mn = o2f(g_bmin[d]), mx = o2f(g_bmax[d]);
        lo[d] = mn;
        float w = (mx - mn);
        inv[d] = (w > 0.f) ? (float)GRID / w : 0.f;
    }
}
__device__ __forceinline__ int cell_of(float v, float lo, float inv) {
    int c = (int)((v - lo) * inv);
    return min(max(c, 0), GRID - 1);
}

// ---------------- counts / hierarchical prefix / scatter ----------------
__global__ void cellcount_kernel(const float* __restrict__ coords) {
    int j = blockIdx.x * blockDim.x + threadIdx.x;
    if (j >= NPTS) return;
    float lo[3], inv[3];
    load_grid_params(lo, inv);
    int cx = cell_of(coords[3 * j + 0], lo[0], inv[0]);
    int cy = cell_of(coords[3 * j + 1], lo[1], inv[1]);
    int cz = cell_of(coords[3 * j + 2], lo[2], inv[2]);
    atomicAdd(&g_cellcnt[cx + (cy << 5) + (cz << 10)], 1);
}

__global__ void seg_sum_kernel() {
    __shared__ int wt[8];
    int tid = threadIdx.x, lane = tid & 31, wid = tid >> 5;
    const int4* c4 = (const int4*)g_cellcnt;
    int4 c = c4[blockIdx.x * 256 + tid];
    int s = c.x + c.y + c.z + c.w;
#pragma unroll
    for (int o = 16; o > 0; o >>= 1) s += __shfl_down_sync(0xffffffffu, s, o);
    if (lane == 0) wt[wid] = s;
    __syncthreads();
    if (tid == 0) {
        int t = 0;
#pragma unroll
        for (int w = 0; w < 8; w++) t += wt[w];
        g_segsum[blockIdx.x] = t;
    }
}

__global__ void seg_scan_kernel() {
    int lane = threadIdx.x;
    int v = g_segsum[lane];
    int incl = v;
#pragma unroll
    for (int o = 1; o < 32; o <<= 1) {
        int n = __shfl_up_sync(0xffffffffu, incl, o);
        if (lane >= o) incl += n;
    }
    g_segoff[lane] = incl - v;
    if (lane == 31) g_segoff[32] = incl;
}

__global__ void prefix_write_kernel() {
    __shared__ int wt[8];
    int tid = threadIdx.x, lane = tid & 31, wid = tid >> 5;
    const int4* c4 = (const int4*)g_cellcnt;
    int4 c = c4[blockIdx.x * 256 + tid];
    int s = c.x + c.y + c.z + c.w;
    int incl = s;
#pragma unroll
    for (int o = 1; o < 32; o <<= 1) {
        int n = __shfl_up_sync(0xffffffffu, incl, o);
        if (lane >= o) incl += n;
    }
    if (lane == 31) wt[wid] = incl;
    __syncthreads();
    int woff = 0;
    for (int w = 0; w < wid; w++) woff += wt[w];
    int base = g_segoff[blockIdx.x] + woff + incl - s;
    int4 o4;
    o4.x = base;
    o4.y = base + c.x;
    o4.z = base + c.x + c.y;
    o4.w = base + c.x + c.y + c.z;
    ((int4*)g_cellstart)[blockIdx.x * 256 + tid] = o4;
    ((int4*)g_cursor)[blockIdx.x * 256 + tid] = o4;
    if (blockIdx.x == 31 && tid == 255) g_cellstart[NC] = g_segoff[32];
}

__global__ void scatter_kernel(const float* __restrict__ coords) {
    int j = blockIdx.x * blockDim.x + threadIdx.x;
    if (j >= NPTS) return;
    float lo[3], inv[3];
    load_grid_params(lo, inv);
    float x = coords[3 * j + 0], y = coords[3 * j + 1], z = coords[3 * j + 2];
    int c = cell_of(x, lo[0], inv[0]) + (cell_of(y, lo[1], inv[1]) << 5)
          + (cell_of(z, lo[2], inv[2]) << 10);
    int pos = atomicAdd(&g_cursor[c], 1);
    g_pts[pos] = make_float4(x, y, z, __int_as_float(j));
}

// ---------------- SAT ----------------
__global__ void __launch_bounds__(128) sat_x_kernel() {
    int t = blockIdx.x * 128 + threadIdx.x;
    int4* p = (int4*)(g_cellcnt + (t << 5));
    int4 v[8];
#pragma unroll
    for (int u = 0; u < 8; u++) v[u] = p[u];
    int acc = 0;
#pragma unroll
    for (int u = 0; u < 8; u++) {
        v[u].x += acc; v[u].y += v[u].x; v[u].z += v[u].y; v[u].w += v[u].z;
        acc = v[u].w;
    }
#pragma unroll
    for (int u = 0; u < 8; u++) p[u] = v[u];
}
__global__ void __launch_bounds__(128) sat_y_kernel() {
    int t = blockIdx.x * 128 + threadIdx.x;
    int x = t & 31, z = t >> 5;
    int b = x + (z << 10);
    int a[32];
#pragma unroll
    for (int y = 0; y < GRID; y++) a[y] = g_cellcnt[b + (y << 5)];
    int acc = 0;
#pragma unroll
    for (int y = 0; y < GRID; y++) { acc += a[y]; a[y] = acc; }
#pragma unroll
    for (int y = 0; y < GRID; y++) g_cellcnt[b + (y << 5)] = a[y];
}
__global__ void __launch_bounds__(128) sat_z_kernel() {
    int t = blockIdx.x * 128 + threadIdx.x;
    int a[32];
#pragma unroll
    for (int z = 0; z < GRID; z++) a[z] = g_cellcnt[t + (z << 10)];
    int acc = 0;
#pragma unroll
    for (int z = 0; z < GRID; z++) { acc += a[z]; a[z] = acc; }
#pragma unroll
    for (int z = 0; z < GRID; z++) g_cellcnt[t + (z << 10)] = a[z];
}

__device__ __forceinline__ int satv(int x, int y, int z) {
    if (x < 0 || y < 0 || z < 0) return 0;
    return g_cellcnt[x + (y << 5) + (z << 10)];
}
__device__ __forceinline__ int boxcount(int x0, int x1, int y0, int y1, int z0, int z1) {
    return satv(x1, y1, z1) - satv(x0 - 1, y1, z1) - satv(x1, y0 - 1, z1) - satv(x1, y1, z0 - 1)
         + satv(x0 - 1, y0 - 1, z1) + satv(x0 - 1, y1, z0 - 1) + satv(x1, y0 - 1, z0 - 1)
         - satv(x0 - 1, y0 - 1, z0 - 1);
}

// ---------------- permutation via rank (proven) ----------------
__global__ void permA_kernel(unsigned int k0, unsigned int k1) {
    int l = blockIdx.x * blockDim.x + threadIdx.x;
    if (l < HALF_N) {
        unsigned int y0, y1;
        tf2x32(k0, k1, (unsigned int)l, (unsigned int)(l + HALF_N), y0, y1);
        g_packed1[l]          = ((unsigned long long)y0 << 14) | (unsigned int)l;
        g_packed1[l + HALF_N] = ((unsigned long long)y1 << 14) | (unsigned int)(l + HALF_N);
    }
}
__global__ void rank_partial_kernel(const unsigned long long* __restrict__ keys,
                                    int* __restrict__ rank) {
    __shared__ unsigned long long tile[256];
    int j = blockIdx.x * 256 + threadIdx.x;
    unsigned long long mk = __ldg(&keys[j]);
    int base0 = blockIdx.y * SEGLEN;
    int cnt = 0;
    for (int base = base0; base < base0 + SEGLEN; base += 256) {
        tile[threadIdx.x] = __ldg(&keys[base + threadIdx.x]);
        __syncthreads();
#pragma unroll 8
        for (int u = 0; u < 256; u++) cnt += (tile[u] < mk) ? 1 : 0;
        __syncthreads();
    }
    atomicAdd(&rank[j], cnt);
}
__global__ void permB_gen_kernel(unsigned int k0, unsigned int k1) {
    int j = blockIdx.x * blockDim.x + threadIdx.x;
    int r = g_rank1[j];
    int lane = (r < HALF_N) ? r : (r - HALF_N);
    unsigned int y0, y1;
    tf2x32(k0, k1, (unsigned int)lane, (unsigned int)(lane + HALF_N), y0, y1);
    unsigned int bits = (r < HALF_N) ? y0 : y1;
    g_packed2[j] = ((unsigned long long)bits << 14) | (unsigned int)r;
}
__global__ void permC_gen_kernel() {
    int j = blockIdx.x * blockDim.x + threadIdx.x;
    int r2 = g_rank2[j];
    if (r2 < SAMPLE_N) g_sample_idx[r2] = j;
}

// ---------------- gather ----------------
__global__ void gather_kernel(const float* __restrict__ emb, const float* __restrict__ coords) {
    int stride = gridDim.x * blockDim.x;
    int gid = blockIdx.x * blockDim.x + threadIdx.x;
    for (int t = gid; t < SAMPLE_N * DIM; t += stride) {
        int s = t / DIM, d = t - s * DIM;
        g_embsT[d * SAMPLE_N + s] = emb[(long)g_sample_idx[s] * DIM + d];
    }
    for (int t = gid; t < SAMPLE_N * CDIM; t += stride) {
        int s = t / CDIM, c = t - s * CDIM;
        g_csampT[c * SAMPLE_N + s] = coords[(long)g_sample_idx[s] * CDIM + c];
    }
}

// ---------------- reductions ----------------
__device__ void block_reduce_atomic_256(double v, double* target, double* swarp) {
    int lane = threadIdx.x & 31, wid = threadIdx.x >> 5;
#pragma unroll
    for (int o = 16; o > 0; o >>= 1) v += __shfl_down_sync(0xffffffffu, v, o);
    if (lane == 0) swarp[wid] = v;
    __syncthreads();
    if (wid == 0) {
        double r = (lane < 8) ? swarp[lane] : 0.0;
#pragma unroll
        for (int o = 4; o > 0; o >>= 1) r += __shfl_down_sync(0xffffffffu, r, o);
        if (lane == 0) atomicAdd(target, r);
    }
    __syncthreads();
}

// ---------------- pearson (proven) ----------------
#define TI 8
__global__ void pearson_kernel(const float* __restrict__ emb, const float* __restrict__ coords) {
    __shared__ float semb[TI][DIM];
    __shared__ float scrd[TI][CDIM];
    __shared__ double swarp[8];
    int i0 = blockIdx.x * TI;
    for (int t = threadIdx.x; t < TI * DIM; t += blockDim.x) {
        int r = t / DIM, d = t - r * DIM;
        semb[r][d] = emb[(long)g_sample_idx[i0 + r] * DIM + d];
    }
    for (int t = threadIdx.x; t < TI * CDIM; t += blockDim.x) {
        int r = t / CDIM, c = t - r * CDIM;
        scrd[r][c] = coords[(long)g_sample_idx[i0 + r] * CDIM + c];
    }
    __syncthreads();

    double se = 0, sc = 0, see = 0, scc = 0, sec = 0;
    for (int j = threadIdx.x; j < SAMPLE_N; j += blockDim.x) {
        float sq[TI];
#pragma unroll
        for (int r = 0; r < TI; r++) sq[r] = 0.f;
#pragma unroll 4
        for (int d = 0; d < DIM; d++) {
            float ej = g_embsT[d * SAMPLE_N + j];
#pragma unroll
            for (int r = 0; r < TI; r++) {
                float df = semb[r][d] - ej;
                sq[r] = fmaf(df, df, sq[r]);
            }
        }
        float cj0 = g_csampT[j];
        float cj1 = g_csampT[SAMPLE_N + j];
        float cj2 = g_csampT[2 * SAMPLE_N + j];
#pragma unroll
        for (int r = 0; r < TI; r++) {
            float d0 = scrd[r][0] - cj0, d1 = scrd[r][1] - cj1, d2 = scrd[r][2] - cj2;
            float cd = sqrtf(fmaf(d0, d0, fmaf(d1, d1, d2 * d2)));
            float ed = sqrtf(sq[r]);
            se += (double)ed;
            sc += (double)cd;
            see += (double)ed * (double)ed;
            scc += (double)cd * (double)cd;
            sec += (double)ed * (double)cd;
        }
    }
    block_reduce_atomic_256(se,  &g_acc[0], swarp);
    block_reduce_atomic_256(sc,  &g_acc[1], swarp);
    block_reduce_atomic_256(see, &g_acc[2], swarp);
    block_reduce_atomic_256(scc, &g_acc[3], swarp);
    block_reduce_atomic_256(sec, &g_acc[4], swarp);
}

// ---------------- flat parallel range collect (128 thr; small-smem variant) ----------------
// Returns M; M > CAPQ means "not collected" (incl. nrows > MAXROWS) -> caller falls back.
__device__ int collect_range(int x0, int x1, int y0, int y1, int z0, int z1,
                             float q0, float q1, float q2,
                             float* bufD, int* bufI,
                             int* rowoff, int* rowstart, int* warptot) {
    int tid = threadIdx.x, lane = tid & 31, wid = tid >> 5;
    int ny = y1 - y0 + 1, nz = z1 - z0 + 1;
    int nrows = ny * nz;
    if (nrows > MAXROWS) return CAPQ + 1;      // uniform: all threads same nrows
    int chunk = (nrows + 127) >> 7;            // <= 4
    int myv[4];
    int s = 0;
    for (int u = 0; u < chunk; u++) {
        int r = tid * chunk + u;
        int v = 0;
        if (r < nrows) {
            int y = y0 + (r % ny), z = z0 + (r / ny);
            int c = x0 + (y << 5) + (z << 10);
            int cs = g_cellstart[c];
            int ce = g_cellstart[c + (x1 - x0) + 1];
            rowstart[r] = cs;
            v = ce - cs;
        }
        myv[u] = v;
        s += v;
    }
    int v2 = s;
#pragma unroll
    for (int o = 1; o < 32; o <<= 1) {
        int n = __shfl_up_sync(0xffffffffu, v2, o);
        if (lane >= o) v2 += n;
    }
    if (lane == 31) warptot[wid] = v2;
    __syncthreads();
    int woff = 0;
    for (int w = 0; w < wid; w++) woff += warptot[w];
    int run = woff + v2 - s;
    for (int u = 0; u < chunk; u++) {
        int r = tid * chunk + u;
        if (r < nrows) { rowoff[r] = run; run += myv[u]; }
    }
    if (tid == 127) rowoff[nrows] = warptot[0] + warptot[1] + warptot[2] + warptot[3];
    __syncthreads();
    int M = rowoff[nrows];
    if (M > CAPQ) { __syncthreads(); return M; }

    for (int t = tid; t < M; t += 128) {
        int lo = 0, hi = nrows - 1;
        while (lo < hi) {
            int mid = (lo + hi + 1) >> 1;
            if (rowoff[mid] <= t) lo = mid; else hi = mid - 1;
        }
        int p = rowstart[lo] + (t - rowoff[lo]);
        float4 pt = g_pts[p];
        float dx = q0 - pt.x, dy = q1 - pt.y, dz = q2 - pt.z;
        bufD[t] = fmaf(dx, dx, fmaf(dy, dy, dz * dz));
        bufI[t] = __float_as_int(pt.w);
    }
    __syncthreads();
    return M;
}

// O(M²) fallback select (exact, rare)
__device__ float select_rank_slow(const float* bufD, int M, int rank, float* s_tau) {
    int tid = threadIdx.x;
    for (int ii = tid; ii < M; ii += 128) {
        float e = bufD[ii];
        int l = 0, le = 0;
        for (int j2 = 0; j2 < M; j2++) {
            float b = bufD[j2];
            l  += (b < e)  ? 1 : 0;
            le += (b <= e) ? 1 : 0;
        }
        if (l < rank && rank <= le) *s_tau = e;
    }
    __syncthreads();
    return *s_tau;
}

// O(M) exact select (proven R8)
__device__ float select_rank_hist(const float* bufD, int M, int rank,
                                  int* hist, int* warptot,
                                  int* s_bin, int* s_cum, int* s_c, float* s_tau) {
    int tid = threadIdx.x, lane = tid & 31, wid = tid >> 5;
    for (int k = tid; k < 2048; k += 128) hist[k] = 0;
    if (tid == 0) *s_c = 0;
    __syncthreads();
    for (int t = tid; t < M; t += 128)
        atomicAdd(&hist[__float_as_uint(bufD[t]) >> 20], 1);
    __syncthreads();
    {
        int base = tid * 16;
        int h[16], s = 0;
#pragma unroll
        for (int u = 0; u < 16; u++) { h[u] = hist[base + u]; s += h[u]; }
        int v = s;
#pragma unroll
        for (int o = 1; o < 32; o <<= 1) {
            int n = __shfl_up_sync(0xffffffffu, v, o);
            if (lane >= o) v += n;
        }
        if (lane == 31) warptot[wid] = v;
        __syncthreads();
        int woff = 0;
        for (int w = 0; w < wid; w++) woff += warptot[w];
        int incl = woff + v, excl = incl - s;
        if (excl < rank && rank <= incl) {
            int c = excl;
#pragma unroll
            for (int u = 0; u < 16; u++) {
                if (rank <= c + h[u]) { *s_bin = base + u; *s_cum = c; break; }
                c += h[u];
            }
        }
        __syncthreads();
    }
    int b = *s_bin;
    int rb = rank - *s_cum;
    float* cand = (float*)hist;
    __syncthreads();
    int iters = (M + 127) >> 7;
    for (int it = 0; it < iters; it++) {
        int t = (it << 7) + tid;
        float v = 0.f;
        bool in = false;
        if (t < M) {
            v = bufD[t];
            in = ((int)(__float_as_uint(v) >> 20) == b);
        }
        unsigned m = __ballot_sync(0xffffffffu, in);
        if (in) {
            int ldr = __ffs(m) - 1;
            int basep = 0;
            if (lane == ldr) basep = atomicAdd(s_c, __popc(m));
            basep = __shfl_sync(m, basep, ldr);
            int p = basep + __popc(m & ((1u << lane) - 1u));
            if (p < CANDCAP) cand[p] = v;
        }
    }
    __syncthreads();
    int C = *s_c;
    if (C > CANDCAP) return select_rank_slow(bufD, M, rank, s_tau);
    for (int ii = tid; ii < C; ii += 128) {
        float e = cand[ii];
        int l = 0, le = 0;
        for (int j2 = 0; j2 < C; j2++) {
            float bb = cand[j2];
            l  += (bb < e)  ? 1 : 0;
            le += (bb <= e) ? 1 : 0;
        }
        if (l < rb && rb <= le) *s_tau = e;
    }
    __syncthreads();
    return *s_tau;
}

// ---------------- query kernel: 128 thr/row, 8 blocks/SM target ----------------
__global__ void __launch_bounds__(128, 8)
knn_query_kernel(const float* __restrict__ emb, const float* __restrict__ coords) {
    __shared__ float bufD[CAPQ];
    __shared__ int   bufI[CAPQ];
    __shared__ int   rowoff[MAXROWS + 1];
    __shared__ int   rowstart[MAXROWS];
    __shared__ int   hist[2048];
    __shared__ float ei[DIM];
    __shared__ int   warptot[4];
    __shared__ int   s_s1, s_W, s_icnt, s_bin, s_cum, s_c;
    __shared__ float s_tau;
    __shared__ double swarpd[4];

    int tid = threadIdx.x;
    int lane = tid & 31, wid = tid >> 5;

    // spatially-ordered queries (kept from R15; harmless)
    float4 qp = g_pts[blockIdx.x];
    float q0 = qp.x, q1 = qp.y, q2 = qp.z;
    int i = __float_as_int(qp.w);
    if (tid < DIM) ei[tid] = emb[(long)i * DIM + tid];

    float lo[3], inv[3];
    load_grid_params(lo, inv);
    int qcx = cell_of(q0, lo[0], inv[0]);
    int qcy = cell_of(q1, lo[1], inv[1]);
    int qcz = cell_of(q2, lo[2], inv[2]);

    int myc = 0;
    if (tid < 16) {
        int s = tid;
        myc = boxcount(max(qcx - s, 0), min(qcx + s, GRID - 1),
                       max(qcy - s, 0), min(qcy + s, GRID - 1),
                       max(qcz - s, 0), min(qcz + s, GRID - 1));
    }
    unsigned ok = __ballot_sync(0xffffffffu, tid < 16 && myc >= KNN + 2);
    if (tid == 0) {
        if (ok) s_s1 = __ffs(ok) - 1;
        else {
            int s = 16;
            while (s < GRID && boxcount(max(qcx - s, 0), min(qcx + s, GRID - 1),
                                        max(qcy - s, 0), min(qcy + s, GRID - 1),
                                        max(qcz - s, 0), min(qcz + s, GRID - 1)) < KNN + 2) s++;
            s_s1 = s;
        }
    }
    __syncthreads();
    int s1 = s_s1 + 1;

    int bx0 = max(qcx - s1, 0), bx1 = min(qcx + s1, GRID - 1);
    int by0 = max(qcy - s1, 0), by1 = min(qcy + s1, GRID - 1);
    int bz0 = max(qcz - s1, 0), bz1 = min(qcz + s1, GRID - 1);

    int M = collect_range(bx0, bx1, by0, by1, bz0, bz1, q0, q1, q2,
                          bufD, bufI, rowoff, rowstart, warptot);
    bool overflow = (M > CAPQ);
    float tau = 0.f;
    bool done = false;

    if (!overflow) {
        float tau1 = select_rank_hist(bufD, M, KNN + 1, hist, warptot,
                                      &s_bin, &s_cum, &s_c, &s_tau);
        float R = sqrtf(tau1) * 1.0001f + 1e-7f;

        float w0 = 1.f / inv[0], w1 = 1.f / inv[1], w2 = 1.f / inv[2];
        bool cont = true;
        if (bx0 > 0)        cont = cont && (q0 - R >= lo[0] + bx0 * w0);
        if (bx1 < GRID - 1) cont = cont && (q0 + R <= lo[0] + (bx1 + 1) * w0);
        if (by0 > 0)        cont = cont && (q1 - R >= lo[1] + by0 * w1);
        if (by1 < GRID - 1) cont = cont && (q1 + R <= lo[1] + (by1 + 1) * w1);
        if (bz0 > 0)        cont = cont && (q2 - R >= lo[2] + bz0 * w2);
        if (bz1 < GRID - 1) cont = cont && (q2 + R <= lo[2] + (bz1 + 1) * w2);

        if (cont) {
            tau = tau1;
            done = true;
        } else {
            int x0 = min(max((int)floorf((q0 - R - lo[0]) * inv[0]), 0), GRID - 1);
            int x1 = min(max((int)floorf((q0 + R - lo[0]) * inv[0]), 0), GRID - 1);
            int y0 = min(max((int)floorf((q1 - R - lo[1]) * inv[1]), 0), GRID - 1);
            int y1 = min(max((int)floorf((q1 + R - lo[1]) * inv[1]), 0), GRID - 1);
            int z0 = min(max((int)floorf((q2 - R - lo[2]) * inv[2]), 0), GRID - 1);
            int z1 = min(max((int)floorf((q2 + R - lo[2]) * inv[2]), 0), GRID - 1);
            __syncthreads();
            M = collect_range(x0, x1, y0, y1, z0, z1, q0, q1, q2,
                              bufD, bufI, rowoff, rowstart, warptot);
            overflow = (M > CAPQ);
            if (!overflow) {
                tau = select_rank_hist(bufD, M, KNN + 1, hist, warptot,
                                       &s_bin, &s_cum, &s_c, &s_tau);
                done = true;
            }
        }
    }

    double acc = 0.0;
    if (done) {
        if (tid == 0) s_W = 0;
        __syncthreads();
        float* wd2 = (float*)rowoff;
        int*   wix = rowstart;
        int iters = (M + 127) >> 7;
        for (int it2 = 0; it2 < iters; it2++) {
            int t = (it2 << 7) + tid;
            float d2 = 0.f; int idx = 0;
            bool win = false;
            if (t < M) {
                d2 = bufD[t];
                idx = bufI[t];
                win = (d2 <= tau) && (idx != i);
            }
            unsigned m = __ballot_sync(0xffffffffu, win);
            if (win) {
                int ldr = __ffs(m) - 1;
                int basep = 0;
                if (lane == ldr) basep = atomicAdd(&s_W, __popc(m));
                basep = __shfl_sync(m, basep, ldr);
                int p = basep + __popc(m & ((1u << lane) - 1u));
                if (p < MAXROWS) { wd2[p] = d2; wix[p] = idx; }
            }
        }
        __syncthreads();
        int W = min(s_W, MAXROWS);
        for (int w = tid; w < W; w += 128) {
            float t = sqrtf(wd2[w]);
            int j = wix[w];
            const float4* e4 = (const float4*)(emb + (long)j * DIM);
            const float4* a4 = (const float4*)ei;
            float s = 0.f;
#pragma unroll
            for (int u = 0; u < DIM / 4; u++) {
                float4 a = a4[u];
                float4 b = e4[u];
                float d0 = a.x - b.x, dd1 = a.y - b.y, dd2 = a.z - b.z, d3 = a.w - b.w;
                s = fmaf(d0, d0, fmaf(dd1, dd1, fmaf(dd2, dd2, fmaf(d3, d3, s))));
            }
            float p = sqrtf(s);
            float df = p - t;
            acc += (double)(df * df * expf(-GAMMA * t));
        }
    } else {
        unsigned int lob = 0u, hib = 0x7F800000u;
        while (lob < hib) {
            unsigned int mid = (lob + hib) >> 1;
            float midf = __uint_as_float(mid);
            int c = 0;
            for (int j = tid; j < NPTS; j += 128) {
                float dx = q0 - coords[3 * j], dy = q1 - coords[3 * j + 1], dz = q2 - coords[3 * j + 2];
                float d2 = fmaf(dx, dx, fmaf(dy, dy, dz * dz));
                c += (d2 <= midf) ? 1 : 0;
            }
#pragma unroll
            for (int o = 16; o > 0; o >>= 1) c += __shfl_down_sync(0xffffffffu, c, o);
            if (lane == 0) warptot[wid] = c;
            __syncthreads();
            if (tid == 0) s_icnt = warptot[0] + warptot[1] + warptot[2] + warptot[3];
            __syncthreads();
            if (s_icnt >= KNN + 1) hib = mid; else lob = mid + 1;
        }
        float tf = __uint_as_float(lob);
        for (int j = tid; j < NPTS; j += 128) {
            float dx = q0 - coords[3 * j], dy = q1 - coords[3 * j + 1], dz = q2 - coords[3 * j + 2];
            float d2 = fmaf(dx, dx, fmaf(dy, dy, dz * dz));
            if (d2 <= tf && j != i) {
                float t = sqrtf(d2);
                const float4* e4 = (const float4*)(emb + (long)j * DIM);
                const float4* a4 = (const float4*)ei;
                float s = 0.f;
#pragma unroll
                for (int u = 0; u < DIM / 4; u++) {
                    float4 a = a4[u];
                    float4 b = e4[u];
                    float d0 = a.x - b.x, dd1 = a.y - b.y, dd2 = a.z - b.z, d3 = a.w - b.w;
                    s = fmaf(d0, d0, fmaf(dd1, dd1, fmaf(dd2, dd2, fmaf(d3, d3, s))));
                }
                float p = sqrtf(s);
                float df = p - t;
                acc += (double)(df * df * expf(-GAMMA * t));
            }
        }
    }

#pragma unroll
    for (int o = 16; o > 0; o >>= 1) acc += __shfl_down_sync(0xffffffffu, acc, o);
    if (lane == 0) swarpd[wid] = acc;
    __syncthreads();
    if (tid == 0) {
        double r = swarpd[0] + swarpd[1] + swarpd[2] + swarpd[3];
        atomicAdd(&g_acc[5], r);
    }
}

// ---------------- finalize ----------------
__global__ void finalize_kernel(float* out) {
    double M = (double)SAMPLE_N * (double)SAMPLE_N;
    double se = g_acc[0], sc = g_acc[1], see = g_acc[2], scc = g_acc[3], sec = g_acc[4];
    double ls = g_acc[5];
    double me = se / M, mc = sc / M;
    double cov = sec / M - me * mc;
    double ve = see / M - me * me;
    double vc = scc / M - mc * mc;
    double es = sqrt(ve + 1e-8);
    double cs = sqrt(vc + 1e-8);
    double pearson = cov / (es * cs + 1e-8);
    double local = ls / ((double)NPTS * (double)KNN);
    out[0] = (float)((1.0 - pearson) + 0.5 * local);
}

// ---------------- launch ----------------
extern "C" void kernel_launch(void* const* d_in, const int* in_sizes, int n_in,
                              void* d_out, int out_size) {
    const float* emb;
    const float* coords;
    if (in_sizes[0] == NPTS * DIM) {
        emb = (const float*)d_in[0];
        coords = (const float*)d_in[1];
    } else {
        emb = (const float*)d_in[1];
        coords = (const float*)d_in[0];
    }
    float* out = (float*)d_out;

    unsigned int a0, b0, a1, b1;
    tf2x32(0u, 42u, 0u, 2u, a0, b0);
    tf2x32(0u, 42u, 1u, 3u, a1, b1);
    unsigned int c0, d0, c1, d1;
    tf2x32(a0, a1, 0u, 2u, c0, d0);
    tf2x32(a0, a1, 1u, 3u, c1, d1);

    unsigned long long* p1; cudaGetSymbolAddress((void**)&p1, g_packed1);
    unsigned long long* p2; cudaGetSymbolAddress((void**)&p2, g_packed2);
    int* r1; cudaGetSymbolAddress((void**)&r1, g_rank1);
    int* r2; cudaGetSymbolAddress((void**)&r2, g_rank2);
    dim3 rg(NPTS / 256, SEG);

    bool fork = g_sp.ok;
    cudaStream_t sm = 0;
    cudaStream_t ss = fork ? g_sp.side : (cudaStream_t)0;

    init_kernel<<<NPTS / 256, 256, 0, sm>>>();

    if (fork) {
        cudaEventRecord(g_sp.evF, sm);
        cudaStreamWaitEvent(ss, g_sp.evF, 0);
    }

    // ---- Chain B (side): permutation -> gather -> pearson ----
    permA_kernel<<<HALF_N / 256, 256, 0, ss>>>(b0, b1);
    rank_partial_kernel<<<rg, 256, 0, ss>>>(p1, r1);
    permB_gen_kernel<<<NPTS / 256, 256, 0, ss>>>(d0, d1);
    rank_partial_kernel<<<rg, 256, 0, ss>>>(p2, r2);
    permC_gen_kernel<<<NPTS / 256, 256, 0, ss>>>();
    gather_kernel<<<160, 256, 0, ss>>>(emb, coords);
    pearson_kernel<<<SAMPLE_N / TI, 256, 0, ss>>>(emb, coords);

    // ---- Chain A (main): grid build -> knn ----
    bbox_kernel<<<NPTS / 256, 256, 0, sm>>>(coords);
    cellcount_kernel<<<NPTS / 256, 256, 0, sm>>>(coords);
    seg_sum_kernel<<<32, 256, 0, sm>>>();
    seg_scan_kernel<<<1, 32, 0, sm>>>();
    prefix_write_kernel<<<32, 256, 0, sm>>>();
    scatter_kernel<<<NPTS / 256, 256, 0, sm>>>(coords);
    sat_x_kernel<<<8, 128, 0, sm>>>();
    sat_y_kernel<<<8, 128, 0, sm>>>();
    sat_z_kernel<<<8, 128, 0, sm>>>();
    knn_query_kernel<<<NPTS, 128, 0, sm>>>(emb, coords);

    if (fork) {
        cudaEventRecord(g_sp.evJ, ss);
        cudaStreamWaitEvent(sm, g_sp.evJ, 0);
    }

    finalize_kernel<<<1, 1, 0, sm>>>(out);
}